// round 4
// baseline (speedup 1.0000x reference)
#include <cuda_runtime.h>
#include <cstdint>

typedef unsigned long long u64;

#define NB   8192
#define SS   64
#define NXX  4
#define NSF  5
#define HH   32
#define WPB  4          // warps per block
#define SPW  2          // batch streams per warp
#define BPB  (WPB*SPW)  // 8 batch elements per block
#define CH   4          // layer-2 time chunk
#define FULLMASK 0xffffffffu

// ---------- packed f32x2 helpers ----------
static __device__ __forceinline__ u64 ffma2(u64 a, u64 b, u64 c) {
    u64 d; asm("fma.rn.f32x2 %0, %1, %2, %3;" : "=l"(d) : "l"(a), "l"(b), "l"(c)); return d;
}
static __device__ __forceinline__ u64 add2(u64 a, u64 b) {
    u64 d; asm("add.rn.f32x2 %0, %1, %2;" : "=l"(d) : "l"(a), "l"(b)); return d;
}
static __device__ __forceinline__ u64 pk2(float lo, float hi) {
    u64 r; asm("mov.b64 %0, {%1, %2};" : "=l"(r) : "f"(lo), "f"(hi)); return r;
}
static __device__ __forceinline__ void up2(u64 v, float& lo, float& hi) {
    asm("mov.b64 {%0, %1}, %2;" : "=f"(lo), "=f"(hi) : "l"(v));
}

static __device__ __forceinline__ float sigm(float x) {
    return __fdividef(1.0f, 1.0f + __expf(-x));
}
static __device__ __forceinline__ float tanhfast(float x) {
    float ax = fabsf(x);
    float e  = __expf(-2.0f * ax);
    float r  = __fdividef(1.0f - e, 1.0f + e);
    return copysignf(r, x);
}

// ---- shared memory byte offsets ----
#define OFF_GP   0
#define OFF_KF   16896
#define OFF_SY   33408
#define OFF_SHD  (33408 + 65536)
#define OFF_SX   (OFF_SHD + 4096)
#define OFF_SWI  (OFF_SX + 8192)
#define SMEM_BYTES (OFF_SWI + 2048)

__global__ void __launch_bounds__(WPB * 32)
lstm_fused4(const float* __restrict__ x_main,
            const float* __restrict__ x_sfc,
            const float* __restrict__ w_sfc1, const float* __restrict__ b_sfc1,
            const float* __restrict__ w_sfc2, const float* __restrict__ b_sfc2,
            const float* __restrict__ w_ih1,  const float* __restrict__ w_hh1,
            const float* __restrict__ b_ih1,  const float* __restrict__ b_hh1,
            const float* __restrict__ w_ih2,  const float* __restrict__ w_hh2,
            const float* __restrict__ b_ih2,  const float* __restrict__ b_hh2,
            const float* __restrict__ w_out,  const float* __restrict__ b_out,
            float* __restrict__ out)
{
    extern __shared__ char smem[];
    float* gpf  = (float*)(smem + OFF_GP);
    ulonglong2* gp2 = (ulonglong2*)(smem + OFF_GP);
    float* kff  = (float*)(smem + OFF_KF);
    ulonglong2* kf2 = (ulonglong2*)(smem + OFF_KF);
    float* sy   = (float*)(smem + OFF_SY);
    u64*   shd  = (u64*)(smem + OFF_SHD);
    float* sx   = (float*)(smem + OFF_SX);
    float* swi  = (float*)(smem + OFF_SWI);

    const int tid  = threadIdx.x;
    const int wid  = tid >> 5;
    const int lane = tid & 31;
    const int bbase = blockIdx.x * BPB + wid * SPW;
    const int ls0   = wid * SPW;

    // ---- stage: w_hh1 -> gp (gate-pair), w_ih2 -> kf (k-format), x, w_ih1 ----
    #pragma unroll 4
    for (int i = tid; i < 4096; i += WPB * 32) {
        const int row = i >> 5, col = i & 31;
        const float v = w_hh1[i];
        const int T = row >> 6, half = (row >> 5) & 1, j = row & 31;
        const int k2 = col >> 1, par = col & 1;
        gpf[(((T * 16 + k2) * 33) + j) * 4 + par * 2 + half] = v;
    }
    #pragma unroll 4
    for (int i = tid; i < 4096; i += WPB * 32) {
        const int row = i >> 5, col = i & 31;
        const float v = w_ih2[i];
        const int qq = col >> 2, sub = col & 3;
        kff[(qq * 129 + row) * 4 + sub] = v;
    }
    for (int i = tid; i < BPB * SS * NXX; i += WPB * 32)
        sx[i] = x_main[(size_t)blockIdx.x * (BPB * SS * NXX) + i];
    for (int i = tid; i < 4 * HH * NXX; i += WPB * 32)
        swi[i] = w_ih1[i];
    __syncthreads();

    // ---- layer-1 weights -> registers ----
    u64 WR[64];
    #pragma unroll
    for (int T = 0; T < 2; ++T)
        #pragma unroll
        for (int k2 = 0; k2 < 16; ++k2) {
            ulonglong2 v = gp2[(T * 16 + k2) * 33 + lane];
            WR[T * 32 + 2 * k2]     = v.x;
            WR[T * 32 + 2 * k2 + 1] = v.y;
        }
    u64 xw[8];
    #pragma unroll
    for (int T = 0; T < 2; ++T)
        #pragma unroll
        for (int d = 0; d < 4; ++d)
            xw[T * 4 + d] = pk2(swi[(T * 64 + lane) * 4 + d],
                                swi[(T * 64 + 32 + lane) * 4 + d]);
    const u64 b1if = pk2(b_ih1[lane]      + b_hh1[lane],
                         b_ih1[lane + 32] + b_hh1[lane + 32]);
    const u64 b1go = pk2(b_ih1[lane + 64] + b_hh1[lane + 64],
                         b_ih1[lane + 96] + b_hh1[lane + 96]);

    // ---- initial state from surface MLPs (both streams) ----
    float cst[SPW];
    #pragma unroll
    for (int m = 0; m < SPW; ++m) {
        const int b = bbase + m;
        float a1 = b_sfc1[lane], a2 = b_sfc2[lane];
        #pragma unroll
        for (int k = 0; k < NSF; ++k) {
            const float sv = x_sfc[b * NSF + k];
            a1 += sv * w_sfc1[lane * NSF + k];
            a2 += sv * w_sfc2[lane * NSF + k];
        }
        const float h0 = tanhfast(a1);
        cst[m] = tanhfast(a2);
        shd[((ls0 + m) * 2 + 0) * 32 + lane] = pk2(h0, h0);
    }
    __syncwarp();
    int buf = 0;

    // ================= layer 1: time-reversed scan, 2 streams =================
    #pragma unroll 1
    for (int t = 0; t < SS; ++t) {
        const int s = SS - 1 - t;
        #pragma unroll
        for (int m = 0; m < SPW; ++m) {
            const int ls = ls0 + m;
            const float4 xq = *(const float4*)(sx + ls * (SS * NXX) + s * NXX);
            const u64 xd0 = pk2(xq.x, xq.x), xd1 = pk2(xq.y, xq.y);
            const u64 xd2 = pk2(xq.z, xq.z), xd3 = pk2(xq.w, xq.w);
            u64 aif0 = ffma2(xd0, xw[0], b1if);  aif0 = ffma2(xd1, xw[1], aif0);
            u64 aif1 = ffma2(xd2, xw[2], 0ull);  aif1 = ffma2(xd3, xw[3], aif1);
            u64 ago0 = ffma2(xd0, xw[4], b1go);  ago0 = ffma2(xd1, xw[5], ago0);
            u64 ago1 = ffma2(xd2, xw[6], 0ull);  ago1 = ffma2(xd3, xw[7], ago1);

            const ulonglong2* hp = (const ulonglong2*)(shd + (ls * 2 + buf) * 32);
            #pragma unroll
            for (int q = 0; q < 16; ++q) {       // 16 ulonglong2 = 32 k values
                const ulonglong2 hv = hp[q];
                if (q < 8) {
                    aif0 = ffma2(hv.x, WR[2*q],      aif0); aif0 = ffma2(hv.y, WR[2*q+1],      aif0);
                    ago0 = ffma2(hv.x, WR[32+2*q],   ago0); ago0 = ffma2(hv.y, WR[32+2*q+1],   ago0);
                } else {
                    aif1 = ffma2(hv.x, WR[2*q],      aif1); aif1 = ffma2(hv.y, WR[2*q+1],      aif1);
                    ago1 = ffma2(hv.x, WR[32+2*q],   ago1); ago1 = ffma2(hv.y, WR[32+2*q+1],   ago1);
                }
            }
            float gi, gf, gg, go;
            up2(add2(aif0, aif1), gi, gf);
            up2(add2(ago0, ago1), gg, go);
            const float iv = sigm(gi), fv = sigm(gf);
            const float gv = tanhfast(gg), ov = sigm(go);
            cst[m] = fv * cst[m] + iv * gv;
            const float h = ov * tanhfast(cst[m]);
            sy[ls * (SS * HH) + s * HH + lane] = h;
            shd[(ls * 2 + (buf ^ 1)) * 32 + lane] = pk2(h, h);
        }
        __syncwarp();
        buf ^= 1;
    }

    // ---- re-stage gp with w_hh2 ----
    __syncthreads();
    #pragma unroll 4
    for (int i = tid; i < 4096; i += WPB * 32) {
        const int row = i >> 5, col = i & 31;
        const float v = w_hh2[i];
        const int T = row >> 6, half = (row >> 5) & 1, j = row & 31;
        const int k2 = col >> 1, par = col & 1;
        gpf[(((T * 16 + k2) * 33) + j) * 4 + par * 2 + half] = v;
    }
    __syncthreads();

    // ================= layer 2: forward scan, 2 streams =================
    const u64 b2if = pk2(b_ih2[lane]      + b_hh2[lane],
                         b_ih2[lane + 32] + b_hh2[lane + 32]);
    const u64 b2go = pk2(b_ih2[lane + 64] + b_hh2[lane + 64],
                         b_ih2[lane + 96] + b_hh2[lane + 96]);
    const float wo = w_out[lane];
    const float bo = b_out[0];

    #pragma unroll
    for (int m = 0; m < SPW; ++m) {
        cst[m] = 0.0f;
        shd[((ls0 + m) * 2 + buf) * 32 + lane] = 0ull;
    }
    __syncwarp();

    u64 xgif[SPW][CH], xggo[SPW][CH];

    #pragma unroll 1
    for (int chk = 0; chk < SS / CH; ++chk) {
        const int t0 = chk * CH;

        // ---- phase A: input projection (k-format weights) ----
        #pragma unroll
        for (int g = 0; g < 4; ++g)
            #pragma unroll
            for (int qq = 0; qq < 8; ++qq) {
                ulonglong2 v = kf2[qq * 129 + g * 32 + lane];
                WR[g * 16 + 2 * qq]     = v.x;
                WR[g * 16 + 2 * qq + 1] = v.y;
            }
        #pragma unroll
        for (int m = 0; m < SPW; ++m) {
            const int ls = ls0 + m;
            #pragma unroll
            for (int tt = 0; tt < CH; ++tt) {
                const ulonglong2* yp =
                    (const ulonglong2*)(sy + ls * (SS * HH) + (t0 + tt) * HH);
                u64 a0a = 0ull, a0b = 0ull, a1a = 0ull, a1b = 0ull;
                u64 a2a = 0ull, a2b = 0ull, a3a = 0ull, a3b = 0ull;
                #pragma unroll
                for (int q = 0; q < 8; ++q) {    // 8 ulonglong2 = 32 floats of y
                    const ulonglong2 hv = yp[q];
                    if (q < 4) {
                        a0a = ffma2(hv.x, WR[2*q],    a0a); a0a = ffma2(hv.y, WR[2*q+1],    a0a);
                        a1a = ffma2(hv.x, WR[16+2*q], a1a); a1a = ffma2(hv.y, WR[16+2*q+1], a1a);
                        a2a = ffma2(hv.x, WR[32+2*q], a2a); a2a = ffma2(hv.y, WR[32+2*q+1], a2a);
                        a3a = ffma2(hv.x, WR[48+2*q], a3a); a3a = ffma2(hv.y, WR[48+2*q+1], a3a);
                    } else {
                        a0b = ffma2(hv.x, WR[2*q],    a0b); a0b = ffma2(hv.y, WR[2*q+1],    a0b);
                        a1b = ffma2(hv.x, WR[16+2*q], a1b); a1b = ffma2(hv.y, WR[16+2*q+1], a1b);
                        a2b = ffma2(hv.x, WR[32+2*q], a2b); a2b = ffma2(hv.y, WR[32+2*q+1], a2b);
                        a3b = ffma2(hv.x, WR[48+2*q], a3b); a3b = ffma2(hv.y, WR[48+2*q+1], a3b);
                    }
                }
                float l0, h0_, l1, h1_, l2, h2_, l3, h3_;
                up2(add2(a0a, a0b), l0, h0_);
                up2(add2(a1a, a1b), l1, h1_);
                up2(add2(a2a, a2b), l2, h2_);
                up2(add2(a3a, a3b), l3, h3_);
                xgif[m][tt] = add2(pk2(l0 + h0_, l1 + h1_), b2if);
                xggo[m][tt] = add2(pk2(l2 + h2_, l3 + h3_), b2go);
            }
        }

        // ---- phase B: recurrence (gate-pair weights) ----
        #pragma unroll
        for (int T = 0; T < 2; ++T)
            #pragma unroll
            for (int k2 = 0; k2 < 16; ++k2) {
                ulonglong2 v = gp2[(T * 16 + k2) * 33 + lane];
                WR[T * 32 + 2 * k2]     = v.x;
                WR[T * 32 + 2 * k2 + 1] = v.y;
            }
        #pragma unroll
        for (int tt = 0; tt < CH; ++tt) {
            #pragma unroll
            for (int m = 0; m < SPW; ++m) {
                const int ls = ls0 + m;
                u64 aif0 = xgif[m][tt], aif1 = 0ull;
                u64 ago0 = xggo[m][tt], ago1 = 0ull;
                const ulonglong2* hp = (const ulonglong2*)(shd + (ls * 2 + buf) * 32);
                #pragma unroll
                for (int q = 0; q < 16; ++q) {   // 16 ulonglong2 = 32 k values
                    const ulonglong2 hv = hp[q];
                    if (q < 8) {
                        aif0 = ffma2(hv.x, WR[2*q],    aif0); aif0 = ffma2(hv.y, WR[2*q+1],    aif0);
                        ago0 = ffma2(hv.x, WR[32+2*q], ago0); ago0 = ffma2(hv.y, WR[32+2*q+1], ago0);
                    } else {
                        aif1 = ffma2(hv.x, WR[2*q],    aif1); aif1 = ffma2(hv.y, WR[2*q+1],    aif1);
                        ago1 = ffma2(hv.x, WR[32+2*q], ago1); ago1 = ffma2(hv.y, WR[32+2*q+1], ago1);
                    }
                }
                float gi, gf, gg, go;
                up2(add2(aif0, aif1), gi, gf);
                up2(add2(ago0, ago1), gg, go);
                const float iv = sigm(gi), fv = sigm(gf);
                const float gv = tanhfast(gg), ov = sigm(go);
                cst[m] = fv * cst[m] + iv * gv;
                const float h2 = ov * tanhfast(cst[m]);
                shd[(ls * 2 + (buf ^ 1)) * 32 + lane] = pk2(h2, h2);

                float po = h2 * wo;
                #pragma unroll
                for (int off = 16; off; off >>= 1)
                    po += __shfl_xor_sync(FULLMASK, po, off);
                if (lane == 0) out[(size_t)(bbase + m) * SS + t0 + tt] = po + bo;
            }
            __syncwarp();
            buf ^= 1;
        }
    }
}

extern "C" void kernel_launch(void* const* d_in, const int* in_sizes, int n_in,
                              void* d_out, int out_size)
{
    const float* x_main = (const float*)d_in[0];
    const float* x_sfc  = (const float*)d_in[1];
    const float* w_sfc1 = (const float*)d_in[2];
    const float* b_sfc1 = (const float*)d_in[3];
    const float* w_sfc2 = (const float*)d_in[4];
    const float* b_sfc2 = (const float*)d_in[5];
    const float* w_ih1  = (const float*)d_in[6];
    const float* w_hh1  = (const float*)d_in[7];
    const float* b_ih1  = (const float*)d_in[8];
    const float* b_hh1  = (const float*)d_in[9];
    const float* w_ih2  = (const float*)d_in[10];
    const float* w_hh2  = (const float*)d_in[11];
    const float* b_ih2  = (const float*)d_in[12];
    const float* b_hh2  = (const float*)d_in[13];
    const float* w_out  = (const float*)d_in[14];
    const float* b_out  = (const float*)d_in[15];
    float* out = (float*)d_out;

    static bool attr_set = false;
    if (!attr_set) {
        cudaFuncSetAttribute(lstm_fused4, cudaFuncAttributeMaxDynamicSharedMemorySize, SMEM_BYTES);
        attr_set = true;
    }

    const int blocks = NB / BPB;   // 1024
    lstm_fused4<<<blocks, WPB * 32, SMEM_BYTES>>>(
        x_main, x_sfc, w_sfc1, b_sfc1, w_sfc2, b_sfc2,
        w_ih1, w_hh1, b_ih1, b_hh1,
        w_ih2, w_hh2, b_ih2, b_hh2,
        w_out, b_out, out);
}

// round 5
// speedup vs baseline: 1.2028x; 1.2028x over previous
#include <cuda_runtime.h>
#include <cstdint>

typedef unsigned long long u64;

#define NB   8192
#define SS   64
#define NXX  4
#define NSF  5
#define HH   32
#define WPB  4          // warps per block
#define SPW  2          // batch streams per warp
#define BPB  (WPB*SPW)  // 8 batch elements per block
#define CH   4          // layer-2 time chunk
#define FULLMASK 0xffffffffu

// ---------- packed f32x2 helpers ----------
static __device__ __forceinline__ u64 ffma2(u64 a, u64 b, u64 c) {
    u64 d; asm("fma.rn.f32x2 %0, %1, %2, %3;" : "=l"(d) : "l"(a), "l"(b), "l"(c)); return d;
}
static __device__ __forceinline__ u64 add2(u64 a, u64 b) {
    u64 d; asm("add.rn.f32x2 %0, %1, %2;" : "=l"(d) : "l"(a), "l"(b)); return d;
}
static __device__ __forceinline__ u64 pk2(float lo, float hi) {
    u64 r; asm("mov.b64 %0, {%1, %2};" : "=l"(r) : "f"(lo), "f"(hi)); return r;
}
static __device__ __forceinline__ u64 pklo(float lo) {
    u64 r; asm("mov.b64 %0, {%1, %2};" : "=l"(r) : "f"(lo), "f"(0.0f)); return r;
}
static __device__ __forceinline__ void up2(u64 v, float& lo, float& hi) {
    asm("mov.b64 {%0, %1}, %2;" : "=f"(lo), "=f"(hi) : "l"(v));
}
static __device__ __forceinline__ float hsum2(u64 v) {
    float x, y; up2(v, x, y); return x + y;
}

// ---------- fast activations (MUFU.TANH) ----------
static __device__ __forceinline__ float tanh_ap(float x) {
    float r; asm("tanh.approx.f32 %0, %1;" : "=f"(r) : "f"(x)); return r;
}
static __device__ __forceinline__ float sigm(float x) {
    return fmaf(tanh_ap(0.5f * x), 0.5f, 0.5f);
}

// ---- shared memory (bytes) ----
// w2t : ulonglong2[2][8][128]  layer-2 weights (m=0: w_ih2, m=1: w_hh2)  32768
// sy  : float[8][64*32]        layer-1 outputs                          65536
// hb  : float[8][2][32]        h broadcast double buffers                2048
#define OFF_W2T  0
#define OFF_SY   32768
#define OFF_HB   (32768 + 65536)
#define SMEM_BYTES (OFF_HB + 2048)

__global__ void __launch_bounds__(WPB * 32)
lstm_fused5(const float* __restrict__ x_main,
            const float* __restrict__ x_sfc,
            const float* __restrict__ w_sfc1, const float* __restrict__ b_sfc1,
            const float* __restrict__ w_sfc2, const float* __restrict__ b_sfc2,
            const float* __restrict__ w_ih1,  const float* __restrict__ w_hh1,
            const float* __restrict__ b_ih1,  const float* __restrict__ b_hh1,
            const float* __restrict__ w_ih2,  const float* __restrict__ w_hh2,
            const float* __restrict__ b_ih2,  const float* __restrict__ b_hh2,
            const float* __restrict__ w_out,  const float* __restrict__ b_out,
            float* __restrict__ out)
{
    extern __shared__ char smem[];
    ulonglong2* w2t = (ulonglong2*)(smem + OFF_W2T);   // [(m*8+qq)*128 + row]
    float* sy = (float*)(smem + OFF_SY);
    float* hb = (float*)(smem + OFF_HB);

    const int tid  = threadIdx.x;
    const int wid  = tid >> 5;
    const int lane = tid & 31;
    const int bbase = blockIdx.x * BPB + wid * SPW;
    const int ls0   = wid * SPW;

    // ---- stage layer-2 weights into smem ----
    #pragma unroll 4
    for (int i = tid; i < 2 * 8 * 128; i += WPB * 32) {
        const int m   = i >> 10;
        const int qq  = (i >> 7) & 7;
        const int row = i & 127;
        const float* src = (m ? w_hh2 : w_ih2) + row * HH + qq * 4;
        w2t[i] = *(const ulonglong2*)src;
    }
    __syncthreads();

    // ---- layer-1 weights -> registers (from global, one-time) ----
    // WR[g*16 + 2*qq + j] = pair (w_hh1[g*32+lane][4qq+2j], [4qq+2j+1])
    u64 WR[64];
    #pragma unroll
    for (int g = 0; g < 4; ++g) {
        const int row = g * HH + lane;
        #pragma unroll
        for (int qq = 0; qq < 8; ++qq) {
            ulonglong2 v = *(const ulonglong2*)(w_hh1 + row * HH + qq * 4);
            WR[g * 16 + 2 * qq]     = v.x;
            WR[g * 16 + 2 * qq + 1] = v.y;
        }
    }
    u64 wih[4][2];
    float bias1[4];
    #pragma unroll
    for (int g = 0; g < 4; ++g) {
        const int row = g * HH + lane;
        ulonglong2 vi = *(const ulonglong2*)(w_ih1 + row * NXX);
        wih[g][0] = vi.x;
        wih[g][1] = vi.y;
        bias1[g] = b_ih1[row] + b_hh1[row];
    }

    // ---- initial state from surface MLPs (both streams) ----
    float cst[SPW];
    #pragma unroll
    for (int m = 0; m < SPW; ++m) {
        const int b = bbase + m;
        float a1 = b_sfc1[lane], a2 = b_sfc2[lane];
        #pragma unroll
        for (int k = 0; k < NSF; ++k) {
            const float sv = x_sfc[b * NSF + k];
            a1 += sv * w_sfc1[lane * NSF + k];
            a2 += sv * w_sfc2[lane * NSF + k];
        }
        hb[((ls0 + m) * 2 + 0) * 32 + lane] = tanh_ap(a1);
        cst[m] = tanh_ap(a2);
    }
    __syncwarp();
    int buf = 0;

    // ================= layer 1: time-reversed scan, 2 streams =================
    #pragma unroll 1
    for (int t = 0; t < SS; ++t) {
        const int s = SS - 1 - t;
        #pragma unroll
        for (int m = 0; m < SPW; ++m) {
            const int ls = ls0 + m;
            const ulonglong2 xv =
                *(const ulonglong2*)(x_main + (size_t)(bbase + m) * (SS * NXX) + s * NXX);
            u64 a0 = pklo(bias1[0]);
            u64 a1 = pklo(bias1[1]);
            u64 a2 = pklo(bias1[2]);
            u64 a3 = pklo(bias1[3]);
            a0 = ffma2(xv.x, wih[0][0], a0); a0 = ffma2(xv.y, wih[0][1], a0);
            a1 = ffma2(xv.x, wih[1][0], a1); a1 = ffma2(xv.y, wih[1][1], a1);
            a2 = ffma2(xv.x, wih[2][0], a2); a2 = ffma2(xv.y, wih[2][1], a2);
            a3 = ffma2(xv.x, wih[3][0], a3); a3 = ffma2(xv.y, wih[3][1], a3);

            const ulonglong2* hp = (const ulonglong2*)(hb + (ls * 2 + buf) * 32);
            #pragma unroll
            for (int q = 0; q < 8; ++q) {
                const ulonglong2 hv = hp[q];
                a0 = ffma2(hv.x, WR[2*q],    a0); a0 = ffma2(hv.y, WR[2*q+1],    a0);
                a1 = ffma2(hv.x, WR[16+2*q], a1); a1 = ffma2(hv.y, WR[16+2*q+1], a1);
                a2 = ffma2(hv.x, WR[32+2*q], a2); a2 = ffma2(hv.y, WR[32+2*q+1], a2);
                a3 = ffma2(hv.x, WR[48+2*q], a3); a3 = ffma2(hv.y, WR[48+2*q+1], a3);
            }
            const float iv = sigm(hsum2(a0));
            const float fv = sigm(hsum2(a1));
            const float gv = tanh_ap(hsum2(a2));
            const float ov = sigm(hsum2(a3));
            cst[m] = fv * cst[m] + iv * gv;
            const float h = ov * tanh_ap(cst[m]);
            sy[ls * (SS * HH) + s * HH + lane] = h;
            hb[(ls * 2 + (buf ^ 1)) * 32 + lane] = h;
        }
        __syncwarp();
        buf ^= 1;
    }

    // ================= layer 2: forward scan, 2 streams =================
    float bias2[4];
    #pragma unroll
    for (int g = 0; g < 4; ++g)
        bias2[g] = b_ih2[g * HH + lane] + b_hh2[g * HH + lane];
    const float wo = w_out[lane];
    const float bo = b_out[0];

    #pragma unroll
    for (int m = 0; m < SPW; ++m) {
        cst[m] = 0.0f;
        hb[((ls0 + m) * 2 + buf) * 32 + lane] = 0.0f;
    }
    __syncwarp();

    u64 xgA[SPW][CH], xgB[SPW][CH];   // per-(stream,tt): gates (0,1) and (2,3)

    #pragma unroll 1
    for (int chk = 0; chk < SS / CH; ++chk) {
        const int t0 = chk * CH;

        // ---- phase A: input projection (w_ih2 in WR) ----
        #pragma unroll
        for (int g = 0; g < 4; ++g)
            #pragma unroll
            for (int qq = 0; qq < 8; ++qq) {
                ulonglong2 v = w2t[qq * 128 + g * 32 + lane];
                WR[g * 16 + 2 * qq]     = v.x;
                WR[g * 16 + 2 * qq + 1] = v.y;
            }
        #pragma unroll
        for (int m = 0; m < SPW; ++m) {
            const int ls = ls0 + m;
            #pragma unroll
            for (int tt = 0; tt < CH; ++tt) {
                const ulonglong2* yp =
                    (const ulonglong2*)(sy + ls * (SS * HH) + (t0 + tt) * HH);
                u64 a0 = 0ull, a1 = 0ull, a2 = 0ull, a3 = 0ull;
                #pragma unroll
                for (int q = 0; q < 8; ++q) {
                    const ulonglong2 hv = yp[q];
                    a0 = ffma2(hv.x, WR[2*q],    a0); a0 = ffma2(hv.y, WR[2*q+1],    a0);
                    a1 = ffma2(hv.x, WR[16+2*q], a1); a1 = ffma2(hv.y, WR[16+2*q+1], a1);
                    a2 = ffma2(hv.x, WR[32+2*q], a2); a2 = ffma2(hv.y, WR[32+2*q+1], a2);
                    a3 = ffma2(hv.x, WR[48+2*q], a3); a3 = ffma2(hv.y, WR[48+2*q+1], a3);
                }
                xgA[m][tt] = pk2(hsum2(a0) + bias2[0], hsum2(a1) + bias2[1]);
                xgB[m][tt] = pk2(hsum2(a2) + bias2[2], hsum2(a3) + bias2[3]);
            }
        }

        // ---- phase B: recurrence (w_hh2 in WR) ----
        #pragma unroll
        for (int g = 0; g < 4; ++g)
            #pragma unroll
            for (int qq = 0; qq < 8; ++qq) {
                ulonglong2 v = w2t[1024 + qq * 128 + g * 32 + lane];
                WR[g * 16 + 2 * qq]     = v.x;
                WR[g * 16 + 2 * qq + 1] = v.y;
            }
        #pragma unroll
        for (int tt = 0; tt < CH; ++tt) {
            #pragma unroll
            for (int m = 0; m < SPW; ++m) {
                const int ls = ls0 + m;
                float x0, x1, x2, x3;
                up2(xgA[m][tt], x0, x1);
                up2(xgB[m][tt], x2, x3);
                u64 a0 = pklo(x0);
                u64 a1 = pklo(x1);
                u64 a2 = pklo(x2);
                u64 a3 = pklo(x3);
                const ulonglong2* hp = (const ulonglong2*)(hb + (ls * 2 + buf) * 32);
                #pragma unroll
                for (int q = 0; q < 8; ++q) {
                    const ulonglong2 hv = hp[q];
                    a0 = ffma2(hv.x, WR[2*q],    a0); a0 = ffma2(hv.y, WR[2*q+1],    a0);
                    a1 = ffma2(hv.x, WR[16+2*q], a1); a1 = ffma2(hv.y, WR[16+2*q+1], a1);
                    a2 = ffma2(hv.x, WR[32+2*q], a2); a2 = ffma2(hv.y, WR[32+2*q+1], a2);
                    a3 = ffma2(hv.x, WR[48+2*q], a3); a3 = ffma2(hv.y, WR[48+2*q+1], a3);
                }
                const float iv = sigm(hsum2(a0));
                const float fv = sigm(hsum2(a1));
                const float gv = tanh_ap(hsum2(a2));
                const float ov = sigm(hsum2(a3));
                cst[m] = fv * cst[m] + iv * gv;
                const float h2 = ov * tanh_ap(cst[m]);
                hb[(ls * 2 + (buf ^ 1)) * 32 + lane] = h2;

                float po = h2 * wo;
                #pragma unroll
                for (int off = 16; off; off >>= 1)
                    po += __shfl_xor_sync(FULLMASK, po, off);
                if (lane == 0) out[(size_t)(bbase + m) * SS + t0 + tt] = po + bo;
            }
            __syncwarp();
            buf ^= 1;
        }
    }
}

extern "C" void kernel_launch(void* const* d_in, const int* in_sizes, int n_in,
                              void* d_out, int out_size)
{
    const float* x_main = (const float*)d_in[0];
    const float* x_sfc  = (const float*)d_in[1];
    const float* w_sfc1 = (const float*)d_in[2];
    const float* b_sfc1 = (const float*)d_in[3];
    const float* w_sfc2 = (const float*)d_in[4];
    const float* b_sfc2 = (const float*)d_in[5];
    const float* w_ih1  = (const float*)d_in[6];
    const float* w_hh1  = (const float*)d_in[7];
    const float* b_ih1  = (const float*)d_in[8];
    const float* b_hh1  = (const float*)d_in[9];
    const float* w_ih2  = (const float*)d_in[10];
    const float* w_hh2  = (const float*)d_in[11];
    const float* b_ih2  = (const float*)d_in[12];
    const float* b_hh2  = (const float*)d_in[13];
    const float* w_out  = (const float*)d_in[14];
    const float* b_out  = (const float*)d_in[15];
    float* out = (float*)d_out;

    static bool attr_set = false;
    if (!attr_set) {
        cudaFuncSetAttribute(lstm_fused5, cudaFuncAttributeMaxDynamicSharedMemorySize, SMEM_BYTES);
        attr_set = true;
    }

    const int blocks = NB / BPB;   // 1024
    lstm_fused5<<<blocks, WPB * 32, SMEM_BYTES>>>(
        x_main, x_sfc, w_sfc1, b_sfc1, w_sfc2, b_sfc2,
        w_ih1, w_hh1, b_ih1, b_hh1,
        w_ih2, w_hh2, b_ih2, b_hh2,
        w_out, b_out, out);
}